// round 2
// baseline (speedup 1.0000x reference)
#include <cuda_runtime.h>

#define D      128
#define TWOD   256
#define MAXN   200000
#define NLAYER 5
#define ROWS   64
#define SA_S   132
#define ST_S   260
#define NTHR   256

// scratch: ping buffers for h and agg (allocation-free rule -> __device__ globals)
__device__ float g_h[(long)MAXN * D];
__device__ float g_agg[(long)MAXN * D];

// smem floats for mlp kernel
#define SMEM_FLOATS (ROWS*SA_S + ROWS*ST_S + 32*TWOD + TWOD + D + D)
#define SMEM_BYTES  (SMEM_FLOATS * 4)

__device__ __forceinline__ float4 f4add(float4 a, float4 b) {
    return make_float4(a.x + b.x, a.y + b.y, a.z + b.z, a.w + b.w);
}

// ---------------------------------------------------------------------------
// h = x_emb1[x[:,0]] + x_emb2[x[:,1]] ; agg = h + selfloop_const(layer 0)
// one thread per float4 (node, 4 cols)
// ---------------------------------------------------------------------------
__global__ void embed_kernel(const int* __restrict__ x,
                             const float* __restrict__ xe1,
                             const float* __restrict__ xe2,
                             const float* __restrict__ ee1,
                             const float* __restrict__ ee2,
                             const float* __restrict__ ee3,
                             int n) {
    int idx = blockIdx.x * blockDim.x + threadIdx.x;
    if (idx >= n * (D / 4)) return;
    int node = idx >> 5;
    int j    = idx & 31;
    int a = x[node * 2 + 0];
    int c = x[node * 2 + 1];
    float4 h = f4add(((const float4*)xe1)[a * 32 + j],
                     ((const float4*)xe2)[c * 32 + j]);
    // layer-0 self-loop constant: e_emb1[0][4] + e_emb2[0][0] + e_emb3[0][0]
    float4 cv = f4add(f4add(((const float4*)(ee1 + 4 * D))[j],
                            ((const float4*)ee2)[j]),
                      ((const float4*)ee3)[j]);
    ((float4*)g_h)[idx]   = h;
    ((float4*)g_agg)[idx] = f4add(h, cv);
}

// ---------------------------------------------------------------------------
// scatter: for each real edge e, agg[col[e]] += h[row[e]] + edge_emb(e)
// warp per edge; edge-emb tables staged in smem; vector f32 reduction to L2.
// ---------------------------------------------------------------------------
__global__ void scatter_kernel(const int* __restrict__ ei,
                               const int* __restrict__ ea,
                               const float* __restrict__ e1,
                               const float* __restrict__ e2,
                               const float* __restrict__ e3,
                               int e) {
    __shared__ float s1[7 * D], s2[3 * D], s3[3 * D];
    for (int i = threadIdx.x; i < 7 * D; i += blockDim.x) s1[i] = e1[i];
    for (int i = threadIdx.x; i < 3 * D; i += blockDim.x) s2[i] = e2[i];
    for (int i = threadIdx.x; i < 3 * D; i += blockDim.x) s3[i] = e3[i];
    __syncthreads();

    int lane  = threadIdx.x & 31;
    int warp  = (blockIdx.x * blockDim.x + threadIdx.x) >> 5;
    int nwarp = (gridDim.x * blockDim.x) >> 5;

    for (int ed = warp; ed < e; ed += nwarp) {
        int row = ei[ed];
        int col = ei[e + ed];
        int bt  = ea[ed * 3 + 0];
        int bd  = ea[ed * 3 + 1];
        int bb  = ea[ed * 3 + 2];
        float4 emb = f4add(f4add(*(const float4*)&s1[bt * D + lane * 4],
                                 *(const float4*)&s2[bd * D + lane * 4]),
                           *(const float4*)&s3[bb * D + lane * 4]);
        float4 hv = *(const float4*)(g_h + (long)row * D + lane * 4);
        float4 m  = f4add(emb, hv);
        float* p  = g_agg + (long)col * D + lane * 4;
        asm volatile("red.global.add.v4.f32 [%0], {%1,%2,%3,%4};"
                     :: "l"(p), "f"(m.x), "f"(m.y), "f"(m.z), "f"(m.w)
                     : "memory");
    }
}

// ---------------------------------------------------------------------------
// fused GIN MLP for a 64-row tile:
//   T = relu(agg @ W1 + b1)   [64,256]  (kept in smem, never hits DRAM)
//   O = T @ W2 + b2           [64,128]
//   last layer: out = O ; else: h = relu(O), agg_next = h + c_{l+1}
// ---------------------------------------------------------------------------
__global__ void __launch_bounds__(NTHR, 1)
mlp_kernel(const float* __restrict__ W1, const float* __restrict__ b1,
           const float* __restrict__ W2, const float* __restrict__ b2,
           const float* __restrict__ ee1, const float* __restrict__ ee2,
           const float* __restrict__ ee3, int lnext, int last,
           float* __restrict__ out, int n) {
    extern __shared__ float sm[];
    float* sA  = sm;                      // [64][132]
    float* sT  = sA + ROWS * SA_S;        // [64][260]
    float* sB  = sT + ROWS * ST_S;        // [32][256] (reused for W2 slabs)
    float* sb1 = sB + 32 * TWOD;          // [256]
    float* sb2 = sb1 + TWOD;              // [128]
    float* sc  = sb2 + D;                 // [128] next-layer self-loop const

    int tid  = threadIdx.x;
    int row0 = blockIdx.x * ROWS;

    for (int i = tid; i < TWOD; i += NTHR) sb1[i] = b1[i];
    if (tid < D) {
        sb2[tid] = b2[tid];
        float cv = 0.f;
        if (!last)
            cv = ee1[(lnext * 7 + 4) * D + tid] + ee2[lnext * 3 * D + tid]
               + ee3[lnext * 3 * D + tid];
        sc[tid] = cv;
    }
    // load A tile (agg rows row0..row0+63)
    {
        const float4* gA = (const float4*)g_agg + (long)row0 * (D / 4);
        for (int i = tid; i < ROWS * (D / 4); i += NTHR) {
            int r = i >> 5, c = i & 31;
            float4 v = make_float4(0.f, 0.f, 0.f, 0.f);
            if (row0 + r < n) v = gA[i];
            *(float4*)&sA[r * SA_S + c * 4] = v;
        }
    }

    int ty = tid >> 4, tx = tid & 15;  // 16x16 thread grid

    // ---- stage 1: T = relu(A @ W1 + b1), 4 rows x 16 cols per thread ----
    float acc1[4][16];
#pragma unroll
    for (int i = 0; i < 4; ++i)
#pragma unroll
        for (int j = 0; j < 16; ++j) acc1[i][j] = 0.f;

    for (int s = 0; s < 4; ++s) {
        __syncthreads();
        const float4* gB = (const float4*)(W1 + s * 32 * TWOD);
#pragma unroll
        for (int i = 0; i < 8; ++i)
            ((float4*)sB)[tid + i * NTHR] = gB[tid + i * NTHR];
        __syncthreads();
#pragma unroll 8
        for (int kk = 0; kk < 32; ++kk) {
            float a0 = sA[(ty * 4 + 0) * SA_S + s * 32 + kk];
            float a1 = sA[(ty * 4 + 1) * SA_S + s * 32 + kk];
            float a2 = sA[(ty * 4 + 2) * SA_S + s * 32 + kk];
            float a3 = sA[(ty * 4 + 3) * SA_S + s * 32 + kk];
#pragma unroll
            for (int q = 0; q < 4; ++q) {
                float4 b = *(const float4*)&sB[kk * TWOD + q * 64 + tx * 4];
                acc1[0][q*4+0] += a0*b.x; acc1[0][q*4+1] += a0*b.y;
                acc1[0][q*4+2] += a0*b.z; acc1[0][q*4+3] += a0*b.w;
                acc1[1][q*4+0] += a1*b.x; acc1[1][q*4+1] += a1*b.y;
                acc1[1][q*4+2] += a1*b.z; acc1[1][q*4+3] += a1*b.w;
                acc1[2][q*4+0] += a2*b.x; acc1[2][q*4+1] += a2*b.y;
                acc1[2][q*4+2] += a2*b.z; acc1[2][q*4+3] += a2*b.w;
                acc1[3][q*4+0] += a3*b.x; acc1[3][q*4+1] += a3*b.y;
                acc1[3][q*4+2] += a3*b.z; acc1[3][q*4+3] += a3*b.w;
            }
        }
    }

    // write T tile (relu + bias) into smem
#pragma unroll
    for (int rr = 0; rr < 4; ++rr) {
        int r = ty * 4 + rr;
#pragma unroll
        for (int q = 0; q < 4; ++q) {
            int col = q * 64 + tx * 4;
            float4 t;
            t.x = fmaxf(acc1[rr][q*4+0] + sb1[col+0], 0.f);
            t.y = fmaxf(acc1[rr][q*4+1] + sb1[col+1], 0.f);
            t.z = fmaxf(acc1[rr][q*4+2] + sb1[col+2], 0.f);
            t.w = fmaxf(acc1[rr][q*4+3] + sb1[col+3], 0.f);
            *(float4*)&sT[r * ST_S + col] = t;
        }
    }

    // ---- stage 2: O = T @ W2 + b2, 4 rows x 8 cols per thread ----
    float acc2[4][8];
#pragma unroll
    for (int i = 0; i < 4; ++i)
#pragma unroll
        for (int j = 0; j < 8; ++j) acc2[i][j] = 0.f;

    for (int s = 0; s < 8; ++s) {
        __syncthreads();
        const float4* gB = (const float4*)(W2 + s * 32 * D);
#pragma unroll
        for (int i = 0; i < 4; ++i)
            ((float4*)sB)[tid + i * NTHR] = gB[tid + i * NTHR];
        __syncthreads();
#pragma unroll 8
        for (int kk = 0; kk < 32; ++kk) {
            float a0 = sT[(ty * 4 + 0) * ST_S + s * 32 + kk];
            float a1 = sT[(ty * 4 + 1) * ST_S + s * 32 + kk];
            float a2 = sT[(ty * 4 + 2) * ST_S + s * 32 + kk];
            float a3 = sT[(ty * 4 + 3) * ST_S + s * 32 + kk];
#pragma unroll
            for (int q = 0; q < 2; ++q) {
                float4 b = *(const float4*)&sB[kk * D + q * 64 + tx * 4];
                acc2[0][q*4+0] += a0*b.x; acc2[0][q*4+1] += a0*b.y;
                acc2[0][q*4+2] += a0*b.z; acc2[0][q*4+3] += a0*b.w;
                acc2[1][q*4+0] += a1*b.x; acc2[1][q*4+1] += a1*b.y;
                acc2[1][q*4+2] += a1*b.z; acc2[1][q*4+3] += a1*b.w;
                acc2[2][q*4+0] += a2*b.x; acc2[2][q*4+1] += a2*b.y;
                acc2[2][q*4+2] += a2*b.z; acc2[2][q*4+3] += a2*b.w;
                acc2[3][q*4+0] += a3*b.x; acc2[3][q*4+1] += a3*b.y;
                acc2[3][q*4+2] += a3*b.z; acc2[3][q*4+3] += a3*b.w;
            }
        }
    }

    // ---- epilogue ----
#pragma unroll
    for (int rr = 0; rr < 4; ++rr) {
        int r = ty * 4 + rr;
        long grow = (long)row0 + r;
        if (grow >= n) continue;
#pragma unroll
        for (int q = 0; q < 2; ++q) {
            int col = q * 64 + tx * 4;
            float4 o;
            o.x = acc2[rr][q*4+0] + sb2[col+0];
            o.y = acc2[rr][q*4+1] + sb2[col+1];
            o.z = acc2[rr][q*4+2] + sb2[col+2];
            o.w = acc2[rr][q*4+3] + sb2[col+3];
            long off = grow * D + col;
            if (last) {
                *(float4*)(out + off) = o;
            } else {
                float4 h;
                h.x = fmaxf(o.x, 0.f); h.y = fmaxf(o.y, 0.f);
                h.z = fmaxf(o.z, 0.f); h.w = fmaxf(o.w, 0.f);
                *(float4*)(g_h + off) = h;
                float4 cv = *(float4*)&sc[col];
                *(float4*)(g_agg + off) = f4add(h, cv);
            }
        }
    }
}

// ---------------------------------------------------------------------------
extern "C" void kernel_launch(void* const* d_in, const int* in_sizes, int n_in,
                              void* d_out, int out_size) {
    const int*   x   = (const int*)d_in[0];
    const int*   ei  = (const int*)d_in[1];
    const int*   ea  = (const int*)d_in[2];
    const float* xe1 = (const float*)d_in[3];
    const float* xe2 = (const float*)d_in[4];
    const float* ee1 = (const float*)d_in[5];
    const float* ee2 = (const float*)d_in[6];
    const float* ee3 = (const float*)d_in[7];
    const float* W1  = (const float*)d_in[8];
    const float* b1  = (const float*)d_in[9];
    const float* W2  = (const float*)d_in[10];
    const float* b2  = (const float*)d_in[11];
    float* out = (float*)d_out;
    int n = in_sizes[0] / 2;   // x is [N,2]
    int e = in_sizes[1] / 2;   // edge_index is [2,E]

    cudaFuncSetAttribute(mlp_kernel,
                         cudaFuncAttributeMaxDynamicSharedMemorySize, SMEM_BYTES);

    embed_kernel<<<(n * (D / 4) + 255) / 256, 256>>>(x, xe1, xe2, ee1, ee2, ee3, n);

    for (int l = 0; l < NLAYER; ++l) {
        scatter_kernel<<<2368, 256>>>(ei, ea,
                                      ee1 + (long)l * 7 * D,
                                      ee2 + (long)l * 3 * D,
                                      ee3 + (long)l * 3 * D, e);
        int last = (l == NLAYER - 1);
        mlp_kernel<<<(n + ROWS - 1) / ROWS, NTHR, SMEM_BYTES>>>(
            W1 + (long)l * D * TWOD, b1 + (long)l * TWOD,
            W2 + (long)l * TWOD * D, b2 + (long)l * D,
            ee1, ee2, ee3, l + 1, last, out, n);
    }
}

// round 6
// speedup vs baseline: 1.6310x; 1.6310x over previous
#include <cuda_runtime.h>
#include <cuda_bf16.h>
#include <mma.h>

using namespace nvcuda;

#define D      128
#define TWOD   256
#define MAXN   200000
#define NLAYER 5
#define TILE_M 64
#define NTHR   512

// ---------------- device scratch (allocation-free rule) ----------------
__device__ float g_h[(long)MAXN * D];
__device__ float g_agg[(long)MAXN * D];
// pre-transposed + bf16-split weights: w1t[l][n][k] = W1[l][k][n], w2t[l][n][k]=W2[l][k][n]
__device__ unsigned short g_w1t_hi[NLAYER * TWOD * D];
__device__ unsigned short g_w1t_lo[NLAYER * TWOD * D];
__device__ unsigned short g_w2t_hi[NLAYER * D * TWOD];
__device__ unsigned short g_w2t_lo[NLAYER * D * TWOD];

// ---------------- smem byte layout for mlp kernel ----------------
// sA  hi/lo : [64][136] bf16  = 17408 B each
// sT  hi/lo : [64][264] bf16  = 33792 B each
// X region  : W chunks (hi+lo, [256][72] bf16 max = 73728 B) / fp32 C staging
#define OFF_AHI 0
#define OFF_ALO 17408
#define OFF_THI 34816
#define OFF_TLO 68608
#define OFF_X   102400
#define OFF_WLO_REL 36864        /* lo half inside X */
#define OFF_SB1 176128
#define OFF_SB2 177152
#define OFF_SC  177664
#define SMEM_BYTES 178176

#define LDA 136
#define LDT 264
#define LDW 72
#define LDX1 264   /* fp32 staging ldm for C1 [64][264] */
#define LDX2 136   /* fp32 staging ldm for C2 [64][136] */

__device__ __forceinline__ void split_pack(float a, float b,
                                           unsigned& hi, unsigned& lo) {
    __nv_bfloat16 ah = __float2bfloat16(a), bh = __float2bfloat16(b);
    __nv_bfloat16 al = __float2bfloat16(a - __bfloat162float(ah));
    __nv_bfloat16 bl = __float2bfloat16(b - __bfloat162float(bh));
    hi = (unsigned)__bfloat16_as_ushort(ah) |
         ((unsigned)__bfloat16_as_ushort(bh) << 16);
    lo = (unsigned)__bfloat16_as_ushort(al) |
         ((unsigned)__bfloat16_as_ushort(bl) << 16);
}

__device__ __forceinline__ float4 f4add(float4 a, float4 b) {
    return make_float4(a.x + b.x, a.y + b.y, a.z + b.z, a.w + b.w);
}

// ---------------------------------------------------------------------------
// prep: transpose + bf16-split all layer weights once
// ---------------------------------------------------------------------------
__global__ void prep_w(const float* __restrict__ W1, const float* __restrict__ W2) {
    int i = blockIdx.x * blockDim.x + threadIdx.x;
    int tot = NLAYER * TWOD * D;   // same count for both
    if (i >= tot) return;
    {   // w1t[l][n][k] = W1[l][k][n]
        int l = i / (TWOD * D), rem = i % (TWOD * D);
        int nn = rem / D, kk = rem % D;
        float v = W1[(l * D + kk) * TWOD + nn];
        __nv_bfloat16 h = __float2bfloat16(v);
        __nv_bfloat16 lo = __float2bfloat16(v - __bfloat162float(h));
        g_w1t_hi[i] = __bfloat16_as_ushort(h);
        g_w1t_lo[i] = __bfloat16_as_ushort(lo);
    }
    {   // w2t[l][n][k] = W2[l][k][n]
        int l = i / (D * TWOD), rem = i % (D * TWOD);
        int nn = rem / TWOD, kk = rem % TWOD;
        float v = W2[(l * TWOD + kk) * D + nn];
        __nv_bfloat16 h = __float2bfloat16(v);
        __nv_bfloat16 lo = __float2bfloat16(v - __bfloat162float(h));
        g_w2t_hi[i] = __bfloat16_as_ushort(h);
        g_w2t_lo[i] = __bfloat16_as_ushort(lo);
    }
}

// ---------------------------------------------------------------------------
// embed: h = xe1[x0] + xe2[x1] ; agg = h + selfloop_const(layer 0)
// ---------------------------------------------------------------------------
__global__ void embed_kernel(const int* __restrict__ x,
                             const float* __restrict__ xe1,
                             const float* __restrict__ xe2,
                             const float* __restrict__ ee1,
                             const float* __restrict__ ee2,
                             const float* __restrict__ ee3,
                             int n) {
    int idx = blockIdx.x * blockDim.x + threadIdx.x;
    if (idx >= n * (D / 4)) return;
    int node = idx >> 5;
    int j    = idx & 31;
    int a = x[node * 2 + 0];
    int c = x[node * 2 + 1];
    float4 h = f4add(((const float4*)xe1)[a * 32 + j],
                     ((const float4*)xe2)[c * 32 + j]);
    float4 cv = f4add(f4add(((const float4*)(ee1 + 4 * D))[j],
                            ((const float4*)ee2)[j]),
                      ((const float4*)ee3)[j]);
    ((float4*)g_h)[idx]   = h;
    ((float4*)g_agg)[idx] = f4add(h, cv);
}

// ---------------------------------------------------------------------------
// scatter: agg[col[e]] += h[row[e]] + edge_emb(e)   (warp/edge, red.add.v4)
// ---------------------------------------------------------------------------
__global__ void scatter_kernel(const int* __restrict__ ei,
                               const int* __restrict__ ea,
                               const float* __restrict__ e1,
                               const float* __restrict__ e2,
                               const float* __restrict__ e3,
                               int e) {
    __shared__ float s1[7 * D], s2[3 * D], s3[3 * D];
    for (int i = threadIdx.x; i < 7 * D; i += blockDim.x) s1[i] = e1[i];
    for (int i = threadIdx.x; i < 3 * D; i += blockDim.x) s2[i] = e2[i];
    for (int i = threadIdx.x; i < 3 * D; i += blockDim.x) s3[i] = e3[i];
    __syncthreads();

    int lane  = threadIdx.x & 31;
    int warp  = (blockIdx.x * blockDim.x + threadIdx.x) >> 5;
    int nwarp = (gridDim.x * blockDim.x) >> 5;

    for (int ed = warp; ed < e; ed += nwarp) {
        int row = ei[ed];
        int col = ei[e + ed];
        int bt  = ea[ed * 3 + 0];
        int bd  = ea[ed * 3 + 1];
        int bb  = ea[ed * 3 + 2];
        float4 emb = f4add(f4add(*(const float4*)&s1[bt * D + lane * 4],
                                 *(const float4*)&s2[bd * D + lane * 4]),
                           *(const float4*)&s3[bb * D + lane * 4]);
        float4 hv = *(const float4*)(g_h + (long)row * D + lane * 4);
        float4 m  = f4add(emb, hv);
        float* p  = g_agg + (long)col * D + lane * 4;
        asm volatile("red.global.add.v4.f32 [%0], {%1,%2,%3,%4};"
                     :: "l"(p), "f"(m.x), "f"(m.y), "f"(m.z), "f"(m.w)
                     : "memory");
    }
}

// ---------------------------------------------------------------------------
// wmma fused GIN MLP: 64-row tile, 3-pass bf16x2 emulated fp32 GEMMs
// ---------------------------------------------------------------------------
__global__ void __launch_bounds__(NTHR, 1)
mlp_wmma_kernel(int l, int last,
                const float* __restrict__ b1g, const float* __restrict__ b2g,
                const float* __restrict__ ee1, const float* __restrict__ ee2,
                const float* __restrict__ ee3,
                float* __restrict__ out, int n) {
    extern __shared__ char smem[];
    __nv_bfloat16* sAhi = (__nv_bfloat16*)(smem + OFF_AHI);
    __nv_bfloat16* sAlo = (__nv_bfloat16*)(smem + OFF_ALO);
    __nv_bfloat16* sThi = (__nv_bfloat16*)(smem + OFF_THI);
    __nv_bfloat16* sTlo = (__nv_bfloat16*)(smem + OFF_TLO);
    __nv_bfloat16* sWhi = (__nv_bfloat16*)(smem + OFF_X);
    __nv_bfloat16* sWlo = (__nv_bfloat16*)(smem + OFF_X + OFF_WLO_REL);
    float* Xf  = (float*)(smem + OFF_X);
    float* sb1 = (float*)(smem + OFF_SB1);
    float* sb2 = (float*)(smem + OFF_SB2);
    float* sc  = (float*)(smem + OFF_SC);

    int tid = threadIdx.x;
    int wid = tid >> 5;
    int row0 = blockIdx.x * TILE_M;

    // biases + next-layer self-loop const
    for (int i = tid; i < TWOD; i += NTHR) sb1[i] = b1g[l * TWOD + i];
    if (tid < D) {
        sb2[tid] = b2g[l * D + tid];
        float cv = 0.f;
        if (!last) {
            int ln = l + 1;
            cv = ee1[(ln * 7 + 4) * D + tid] + ee2[ln * 3 * D + tid]
               + ee3[ln * 3 * D + tid];
        }
        sc[tid] = cv;
    }

    // ---- load A tile fp32, split to hi/lo bf16 in smem ----
    for (int i = tid; i < TILE_M * (D / 4); i += NTHR) {  // 2048 float4
        int r = i >> 5, c4 = i & 31;
        float4 v = make_float4(0.f, 0.f, 0.f, 0.f);
        if (row0 + r < n)
            v = *(const float4*)(g_agg + ((long)(row0 + r)) * D + c4 * 4);
        unsigned h0, l0, h1, l1;
        split_pack(v.x, v.y, h0, l0);
        split_pack(v.z, v.w, h1, l1);
        *(uint2*)(sAhi + r * LDA + c4 * 4) = make_uint2(h0, h1);
        *(uint2*)(sAlo + r * LDA + c4 * 4) = make_uint2(l0, l1);
    }
    __syncthreads();

    // ================= stage 1: C1[64,256] = A[64,128] @ W1 =================
    // warp grid 2x8; warp tile 32x32; frag grid 2x2
    int wr = wid >> 3, wc = wid & 7;
    wmma::fragment<wmma::accumulator, 16, 16, 16, float> acc1[2][2];
#pragma unroll
    for (int i = 0; i < 2; ++i)
#pragma unroll
        for (int j = 0; j < 2; ++j) wmma::fill_fragment(acc1[i][j], 0.f);

    for (int kc = 0; kc < 2; ++kc) {
        // load W1 k-chunk [256 n][64 k] hi/lo
        for (int i = tid; i < 2048; i += NTHR) {
            int nn = i >> 3, k8 = i & 7;
            long src = ((long)(l * TWOD + nn)) * D + kc * 64 + k8 * 8;
            *(uint4*)(sWhi + nn * LDW + k8 * 8) = *(const uint4*)(g_w1t_hi + src);
            *(uint4*)(sWlo + nn * LDW + k8 * 8) = *(const uint4*)(g_w1t_lo + src);
        }
        __syncthreads();
#pragma unroll
        for (int ks = 0; ks < 4; ++ks) {
            wmma::fragment<wmma::matrix_a, 16, 16, 16, __nv_bfloat16, wmma::row_major> ahi[2], alo[2];
            wmma::fragment<wmma::matrix_b, 16, 16, 16, __nv_bfloat16, wmma::col_major> bhi[2], blo[2];
#pragma unroll
            for (int i = 0; i < 2; ++i) {
                const __nv_bfloat16* pa = sAhi + (wr * 32 + i * 16) * LDA + kc * 64 + ks * 16;
                wmma::load_matrix_sync(ahi[i], pa, LDA);
                wmma::load_matrix_sync(alo[i], pa + (OFF_ALO - OFF_AHI) / 2, LDA);
            }
#pragma unroll
            for (int j = 0; j < 2; ++j) {
                const __nv_bfloat16* pb = sWhi + (wc * 32 + j * 16) * LDW + ks * 16;
                wmma::load_matrix_sync(bhi[j], pb, LDW);
                wmma::load_matrix_sync(blo[j], pb + OFF_WLO_REL / 2, LDW);
            }
#pragma unroll
            for (int i = 0; i < 2; ++i)
#pragma unroll
                for (int j = 0; j < 2; ++j) {
                    wmma::mma_sync(acc1[i][j], ahi[i], bhi[j], acc1[i][j]);
                    wmma::mma_sync(acc1[i][j], ahi[i], blo[j], acc1[i][j]);
                    wmma::mma_sync(acc1[i][j], alo[i], bhi[j], acc1[i][j]);
                }
        }
        __syncthreads();
    }

    // stage C1 fp32 into X (W1 chunks dead now)
#pragma unroll
    for (int i = 0; i < 2; ++i)
#pragma unroll
        for (int j = 0; j < 2; ++j)
            wmma::store_matrix_sync(Xf + (wr * 32 + i * 16) * LDX1 + wc * 32 + j * 16,
                                    acc1[i][j], LDX1, wmma::mem_row_major);
    __syncthreads();

    // convert: T = relu(C1 + b1) -> hi/lo bf16
    for (int i = tid; i < TILE_M * (TWOD / 4); i += NTHR) {  // 4096
        int r = i >> 6, c4 = i & 63;
        float4 v = *(float4*)(Xf + r * LDX1 + c4 * 4);
        float t0 = fmaxf(v.x + sb1[c4 * 4 + 0], 0.f);
        float t1 = fmaxf(v.y + sb1[c4 * 4 + 1], 0.f);
        float t2 = fmaxf(v.z + sb1[c4 * 4 + 2], 0.f);
        float t3 = fmaxf(v.w + sb1[c4 * 4 + 3], 0.f);
        unsigned h0, l0, h1, l1;
        split_pack(t0, t1, h0, l0);
        split_pack(t2, t3, h1, l1);
        *(uint2*)(sThi + r * LDT + c4 * 4) = make_uint2(h0, h1);
        *(uint2*)(sTlo + r * LDT + c4 * 4) = make_uint2(l0, l1);
    }
    __syncthreads();

    // ================= stage 2: C2[64,128] = T[64,256] @ W2 =================
    // warp grid 4x4; warp tile 16x32; frag grid 1x2
    int wr2 = wid >> 2, wc2 = wid & 3;
    wmma::fragment<wmma::accumulator, 16, 16, 16, float> acc2[2];
    wmma::fill_fragment(acc2[0], 0.f);
    wmma::fill_fragment(acc2[1], 0.f);

    for (int kc = 0; kc < 4; ++kc) {
        // load W2 k-chunk [128 n][64 k] hi/lo  (overwrites X / old C1)
        for (int i = tid; i < 1024; i += NTHR) {
            int nn = i >> 3, k8 = i & 7;
            long src = ((long)(l * D + nn)) * TWOD + kc * 64 + k8 * 8;
            *(uint4*)(sWhi + nn * LDW + k8 * 8) = *(const uint4*)(g_w2t_hi + src);
            *(uint4*)(sWlo + nn * LDW + k8 * 8) = *(const uint4*)(g_w2t_lo + src);
        }
        __syncthreads();
#pragma unroll
        for (int ks = 0; ks < 4; ++ks) {
            wmma::fragment<wmma::matrix_a, 16, 16, 16, __nv_bfloat16, wmma::row_major> ahi, alo;
            wmma::fragment<wmma::matrix_b, 16, 16, 16, __nv_bfloat16, wmma::col_major> bhi[2], blo[2];
            const __nv_bfloat16* pa = sThi + (wr2 * 16) * LDT + kc * 64 + ks * 16;
            wmma::load_matrix_sync(ahi, pa, LDT);
            wmma::load_matrix_sync(alo, pa + (OFF_TLO - OFF_THI) / 2, LDT);
#pragma unroll
            for (int j = 0; j < 2; ++j) {
                const __nv_bfloat16* pb = sWhi + (wc2 * 32 + j * 16) * LDW + ks * 16;
                wmma::load_matrix_sync(bhi[j], pb, LDW);
                wmma::load_matrix_sync(blo[j], pb + OFF_WLO_REL / 2, LDW);
            }
#pragma unroll
            for (int j = 0; j < 2; ++j) {
                wmma::mma_sync(acc2[j], ahi, bhi[j], acc2[j]);
                wmma::mma_sync(acc2[j], ahi, blo[j], acc2[j]);
                wmma::mma_sync(acc2[j], alo, bhi[j], acc2[j]);
            }
        }
        __syncthreads();
    }

    // stage C2 fp32 into X
#pragma unroll
    for (int j = 0; j < 2; ++j)
        wmma::store_matrix_sync(Xf + (wr2 * 16) * LDX2 + wc2 * 32 + j * 16,
                                acc2[j], LDX2, wmma::mem_row_major);
    __syncthreads();

    // ---- epilogue: O = C2 + b2 ----
    for (int i = tid; i < TILE_M * (D / 4); i += NTHR) {  // 2048
        int r = i >> 5, c4 = i & 31;
        long grow = (long)row0 + r;
        if (grow >= n) continue;
        float4 v = *(float4*)(Xf + r * LDX2 + c4 * 4);
        float4 o;
        o.x = v.x + sb2[c4 * 4 + 0];
        o.y = v.y + sb2[c4 * 4 + 1];
        o.z = v.z + sb2[c4 * 4 + 2];
        o.w = v.w + sb2[c4 * 4 + 3];
        long off = grow * D + c4 * 4;
        if (last) {
            *(float4*)(out + off) = o;
        } else {
            float4 h;
            h.x = fmaxf(o.x, 0.f); h.y = fmaxf(o.y, 0.f);
            h.z = fmaxf(o.z, 0.f); h.w = fmaxf(o.w, 0.f);
            *(float4*)(g_h + off) = h;
            float4 cv = *(float4*)&sc[c4 * 4];
            *(float4*)(g_agg + off) = f4add(h, cv);
        }
    }
}

// ---------------------------------------------------------------------------
extern "C" void kernel_launch(void* const* d_in, const int* in_sizes, int n_in,
                              void* d_out, int out_size) {
    const int*   x   = (const int*)d_in[0];
    const int*   ei  = (const int*)d_in[1];
    const int*   ea  = (const int*)d_in[2];
    const float* xe1 = (const float*)d_in[3];
    const float* xe2 = (const float*)d_in[4];
    const float* ee1 = (const float*)d_in[5];
    const float* ee2 = (const float*)d_in[6];
    const float* ee3 = (const float*)d_in[7];
    const float* W1  = (const float*)d_in[8];
    const float* b1  = (const float*)d_in[9];
    const float* W2  = (const float*)d_in[10];
    const float* b2  = (const float*)d_in[11];
    float* out = (float*)d_out;
    int n = in_sizes[0] / 2;   // x is [N,2]
    int e = in_sizes[1] / 2;   // edge_index is [2,E]

    cudaFuncSetAttribute(mlp_wmma_kernel,
                         cudaFuncAttributeMaxDynamicSharedMemorySize, SMEM_BYTES);

    prep_w<<<(NLAYER * TWOD * D + 255) / 256, 256>>>(W1, W2);
    embed_kernel<<<(n * (D / 4) + 255) / 256, 256>>>(x, xe1, xe2, ee1, ee2, ee3, n);

    int ntiles = (n + TILE_M - 1) / TILE_M;
    for (int l = 0; l < NLAYER; ++l) {
        scatter_kernel<<<2368, 256>>>(ei, ea,
                                      ee1 + (long)l * 7 * D,
                                      ee2 + (long)l * 3 * D,
                                      ee3 + (long)l * 3 * D, e);
        int last = (l == NLAYER - 1);
        mlp_wmma_kernel<<<ntiles, NTHR, SMEM_BYTES>>>(
            l, last, b1, b2, ee1, ee2, ee3, out, n);
    }
}

// round 7
// speedup vs baseline: 2.0517x; 1.2579x over previous
#include <cuda_runtime.h>
#include <cuda_bf16.h>
#include <mma.h>

using namespace nvcuda;

#define D      128
#define TWOD   256
#define MAXN   200000
#define NLAYER 5
#define TILE_M 64
#define NTHR   256

// ---------------- device scratch (allocation-free rule) ----------------
__device__ float g_h[(long)MAXN * D];
__device__ float g_agg[(long)MAXN * D];
// pre-transposed + bf16-split weights: w1t[l][n][k] = W1[l][k][n], w2t[l][n][k]=W2[l][k][n]
__device__ unsigned short g_w1t_hi[NLAYER * TWOD * D];
__device__ unsigned short g_w1t_lo[NLAYER * TWOD * D];
__device__ unsigned short g_w2t_hi[NLAYER * D * TWOD];
__device__ unsigned short g_w2t_lo[NLAYER * D * TWOD];

// ---------------- smem byte layout (total 108544 -> 2 CTAs/SM) ----------------
// sA hi/lo   : [64][136] bf16 = 17408 each
// sT hi/lo   : [64][136] bf16 = 17408 each   (one column-half of T at a time)
// W region   : hi [128][72] 18432 + lo 18432 = 36864 ; aliased by fp32 X [64][136]=34816
#define OFF_AHI 0
#define OFF_ALO 17408
#define OFF_THI 34816
#define OFF_TLO 52224
#define OFF_W   69632
#define OFF_WLO_REL 18432
#define OFF_SB1 106496
#define OFF_SB2 107520
#define OFF_SC  108032
#define SMEM_BYTES 108544

#define LDA  136
#define LDTH 136
#define LDW  72
#define LDX  136

__device__ __forceinline__ void split_pack(float a, float b,
                                           unsigned& hi, unsigned& lo) {
    __nv_bfloat16 ah = __float2bfloat16(a), bh = __float2bfloat16(b);
    __nv_bfloat16 al = __float2bfloat16(a - __bfloat162float(ah));
    __nv_bfloat16 bl = __float2bfloat16(b - __bfloat162float(bh));
    hi = (unsigned)__bfloat16_as_ushort(ah) |
         ((unsigned)__bfloat16_as_ushort(bh) << 16);
    lo = (unsigned)__bfloat16_as_ushort(al) |
         ((unsigned)__bfloat16_as_ushort(bl) << 16);
}

__device__ __forceinline__ float4 f4add(float4 a, float4 b) {
    return make_float4(a.x + b.x, a.y + b.y, a.z + b.z, a.w + b.w);
}

// ---------------------------------------------------------------------------
// prep: transpose + bf16-split all layer weights once
// ---------------------------------------------------------------------------
__global__ void prep_w(const float* __restrict__ W1, const float* __restrict__ W2) {
    int i = blockIdx.x * blockDim.x + threadIdx.x;
    int tot = NLAYER * TWOD * D;
    if (i >= tot) return;
    {   // w1t[l][n][k] = W1[l][k][n]
        int l = i / (TWOD * D), rem = i % (TWOD * D);
        int nn = rem / D, kk = rem % D;
        float v = W1[(l * D + kk) * TWOD + nn];
        __nv_bfloat16 h = __float2bfloat16(v);
        __nv_bfloat16 lo = __float2bfloat16(v - __bfloat162float(h));
        g_w1t_hi[i] = __bfloat16_as_ushort(h);
        g_w1t_lo[i] = __bfloat16_as_ushort(lo);
    }
    {   // w2t[l][n][k] = W2[l][k][n]
        int l = i / (D * TWOD), rem = i % (D * TWOD);
        int nn = rem / TWOD, kk = rem % TWOD;
        float v = W2[(l * TWOD + kk) * D + nn];
        __nv_bfloat16 h = __float2bfloat16(v);
        __nv_bfloat16 lo = __float2bfloat16(v - __bfloat162float(h));
        g_w2t_hi[i] = __bfloat16_as_ushort(h);
        g_w2t_lo[i] = __bfloat16_as_ushort(lo);
    }
}

// ---------------------------------------------------------------------------
// embed: h = xe1[x0] + xe2[x1] ; agg = h + selfloop_const(layer 0)
// ---------------------------------------------------------------------------
__global__ void embed_kernel(const int* __restrict__ x,
                             const float* __restrict__ xe1,
                             const float* __restrict__ xe2,
                             const float* __restrict__ ee1,
                             const float* __restrict__ ee2,
                             const float* __restrict__ ee3,
                             int n) {
    int idx = blockIdx.x * blockDim.x + threadIdx.x;
    if (idx >= n * (D / 4)) return;
    int node = idx >> 5;
    int j    = idx & 31;
    int a = x[node * 2 + 0];
    int c = x[node * 2 + 1];
    float4 h = f4add(((const float4*)xe1)[a * 32 + j],
                     ((const float4*)xe2)[c * 32 + j]);
    float4 cv = f4add(f4add(((const float4*)(ee1 + 4 * D))[j],
                            ((const float4*)ee2)[j]),
                      ((const float4*)ee3)[j]);
    ((float4*)g_h)[idx]   = h;
    ((float4*)g_agg)[idx] = f4add(h, cv);
}

// ---------------------------------------------------------------------------
// scatter: agg[col[e]] += h[row[e]] + edge_emb(e)   (warp/edge, red.add.v4)
// ---------------------------------------------------------------------------
__global__ void scatter_kernel(const int* __restrict__ ei,
                               const int* __restrict__ ea,
                               const float* __restrict__ e1,
                               const float* __restrict__ e2,
                               const float* __restrict__ e3,
                               int e) {
    __shared__ float s1[7 * D], s2[3 * D], s3[3 * D];
    for (int i = threadIdx.x; i < 7 * D; i += blockDim.x) s1[i] = e1[i];
    for (int i = threadIdx.x; i < 3 * D; i += blockDim.x) s2[i] = e2[i];
    for (int i = threadIdx.x; i < 3 * D; i += blockDim.x) s3[i] = e3[i];
    __syncthreads();

    int lane  = threadIdx.x & 31;
    int warp  = (blockIdx.x * blockDim.x + threadIdx.x) >> 5;
    int nwarp = (gridDim.x * blockDim.x) >> 5;

    for (int ed = warp; ed < e; ed += nwarp) {
        int row = ei[ed];
        int col = ei[e + ed];
        int bt  = ea[ed * 3 + 0];
        int bd  = ea[ed * 3 + 1];
        int bb  = ea[ed * 3 + 2];
        float4 emb = f4add(f4add(*(const float4*)&s1[bt * D + lane * 4],
                                 *(const float4*)&s2[bd * D + lane * 4]),
                           *(const float4*)&s3[bb * D + lane * 4]);
        float4 hv = *(const float4*)(g_h + (long)row * D + lane * 4);
        float4 m  = f4add(emb, hv);
        float* p  = g_agg + (long)col * D + lane * 4;
        asm volatile("red.global.add.v4.f32 [%0], {%1,%2,%3,%4};"
                     :: "l"(p), "f"(m.x), "f"(m.y), "f"(m.z), "f"(m.w)
                     : "memory");
    }
}

// ---------------------------------------------------------------------------
// wmma fused GIN MLP v2: 64-row tile, column-half fusion, 2 CTAs/SM
// ---------------------------------------------------------------------------
__global__ void __launch_bounds__(NTHR, 2)
mlp_wmma_kernel(int l, int last,
                const float* __restrict__ b1g, const float* __restrict__ b2g,
                const float* __restrict__ ee1, const float* __restrict__ ee2,
                const float* __restrict__ ee3,
                float* __restrict__ out, int n) {
    extern __shared__ char smem[];
    __nv_bfloat16* sAhi = (__nv_bfloat16*)(smem + OFF_AHI);
    __nv_bfloat16* sAlo = (__nv_bfloat16*)(smem + OFF_ALO);
    __nv_bfloat16* sThi = (__nv_bfloat16*)(smem + OFF_THI);
    __nv_bfloat16* sTlo = (__nv_bfloat16*)(smem + OFF_TLO);
    __nv_bfloat16* sWhi = (__nv_bfloat16*)(smem + OFF_W);
    __nv_bfloat16* sWlo = (__nv_bfloat16*)(smem + OFF_W + OFF_WLO_REL);
    float* Xf  = (float*)(smem + OFF_W);   // aliases W region
    float* sb1 = (float*)(smem + OFF_SB1);
    float* sb2 = (float*)(smem + OFF_SB2);
    float* sc  = (float*)(smem + OFF_SC);

    int tid = threadIdx.x;
    int wid = tid >> 5;
    int wr = wid >> 2, wc = wid & 3;   // 2x4 warp grid, 32x32 warp tiles
    int row0 = blockIdx.x * TILE_M;

    // biases + next-layer self-loop const
    for (int i = tid; i < TWOD; i += NTHR) sb1[i] = b1g[l * TWOD + i];
    if (tid < D) {
        sb2[tid] = b2g[l * D + tid];
        float cv = 0.f;
        if (!last) {
            int ln = l + 1;
            cv = ee1[(ln * 7 + 4) * D + tid] + ee2[ln * 3 * D + tid]
               + ee3[ln * 3 * D + tid];
        }
        sc[tid] = cv;
    }

    // ---- load A tile fp32, split to hi/lo bf16 in smem ----
    for (int i = tid; i < TILE_M * (D / 4); i += NTHR) {  // 2048 float4 / 256 thr
        int r = i >> 5, c4 = i & 31;
        float4 v = make_float4(0.f, 0.f, 0.f, 0.f);
        if (row0 + r < n)
            v = *(const float4*)(g_agg + ((long)(row0 + r)) * D + c4 * 4);
        unsigned h0, l0, h1, l1;
        split_pack(v.x, v.y, h0, l0);
        split_pack(v.z, v.w, h1, l1);
        *(uint2*)(sAhi + r * LDA + c4 * 4) = make_uint2(h0, h1);
        *(uint2*)(sAlo + r * LDA + c4 * 4) = make_uint2(l0, l1);
    }

    wmma::fragment<wmma::accumulator, 16, 16, 16, float> acc2[2][2];
#pragma unroll
    for (int i = 0; i < 2; ++i)
#pragma unroll
        for (int j = 0; j < 2; ++j) wmma::fill_fragment(acc2[i][j], 0.f);

    // ================= column-half loop =================
    for (int h = 0; h < 2; ++h) {
        // ---- stage 1: C1h[64,128] = A[64,128] @ W1[:, h*128 : h*128+128] ----
        wmma::fragment<wmma::accumulator, 16, 16, 16, float> acc1[2][2];
#pragma unroll
        for (int i = 0; i < 2; ++i)
#pragma unroll
            for (int j = 0; j < 2; ++j) wmma::fill_fragment(acc1[i][j], 0.f);

        for (int kc = 0; kc < 2; ++kc) {
            __syncthreads();   // W region readers (or X/A-split users) done
            for (int i = tid; i < 1024; i += NTHR) {
                int nn = i >> 3, k8 = i & 7;
                long src = ((long)(l * TWOD + h * 128 + nn)) * D + kc * 64 + k8 * 8;
                *(uint4*)(sWhi + nn * LDW + k8 * 8) = *(const uint4*)(g_w1t_hi + src);
                *(uint4*)(sWlo + nn * LDW + k8 * 8) = *(const uint4*)(g_w1t_lo + src);
            }
            __syncthreads();
#pragma unroll
            for (int ks = 0; ks < 4; ++ks) {
                wmma::fragment<wmma::matrix_a, 16, 16, 16, __nv_bfloat16, wmma::row_major> ahi[2], alo[2];
                wmma::fragment<wmma::matrix_b, 16, 16, 16, __nv_bfloat16, wmma::col_major> bhi[2], blo[2];
#pragma unroll
                for (int i = 0; i < 2; ++i) {
                    const __nv_bfloat16* pa = sAhi + (wr * 32 + i * 16) * LDA + kc * 64 + ks * 16;
                    wmma::load_matrix_sync(ahi[i], pa, LDA);
                    wmma::load_matrix_sync(alo[i], pa + (OFF_ALO - OFF_AHI) / 2, LDA);
                }
#pragma unroll
                for (int j = 0; j < 2; ++j) {
                    const __nv_bfloat16* pb = sWhi + (wc * 32 + j * 16) * LDW + ks * 16;
                    wmma::load_matrix_sync(bhi[j], pb, LDW);
                    wmma::load_matrix_sync(blo[j], pb + OFF_WLO_REL / 2, LDW);
                }
#pragma unroll
                for (int i = 0; i < 2; ++i)
#pragma unroll
                    for (int j = 0; j < 2; ++j) {
                        wmma::mma_sync(acc1[i][j], ahi[i], bhi[j], acc1[i][j]);
                        wmma::mma_sync(acc1[i][j], ahi[i], blo[j], acc1[i][j]);
                        wmma::mma_sync(acc1[i][j], alo[i], bhi[j], acc1[i][j]);
                    }
            }
        }

        // stage C1h fp32 into X (aliases W region; all readers must be past it)
        __syncthreads();
#pragma unroll
        for (int i = 0; i < 2; ++i)
#pragma unroll
            for (int j = 0; j < 2; ++j)
                wmma::store_matrix_sync(Xf + (wr * 32 + i * 16) * LDX + wc * 32 + j * 16,
                                        acc1[i][j], LDX, wmma::mem_row_major);
        __syncthreads();

        // convert: Th = relu(C1h + b1[h*128..]) -> hi/lo bf16
        for (int i = tid; i < TILE_M * 32; i += NTHR) {  // 2048 float4
            int r = i >> 5, c4 = i & 31;
            float4 v = *(float4*)(Xf + r * LDX + c4 * 4);
            const float* bb = sb1 + h * 128 + c4 * 4;
            float t0 = fmaxf(v.x + bb[0], 0.f);
            float t1 = fmaxf(v.y + bb[1], 0.f);
            float t2 = fmaxf(v.z + bb[2], 0.f);
            float t3 = fmaxf(v.w + bb[3], 0.f);
            unsigned h0, l0, h1, l1;
            split_pack(t0, t1, h0, l0);
            split_pack(t2, t3, h1, l1);
            *(uint2*)(sThi + r * LDTH + c4 * 4) = make_uint2(h0, h1);
            *(uint2*)(sTlo + r * LDTH + c4 * 4) = make_uint2(l0, l1);
        }

        // ---- stage 2 partial: C2 += Th[64,128] @ W2[h*128 : h*128+128, :] ----
        for (int kc = 0; kc < 2; ++kc) {
            __syncthreads();   // X readers (convert) / prior W2 readers done
            for (int i = tid; i < 1024; i += NTHR) {
                int nn = i >> 3, k8 = i & 7;
                long src = ((long)(l * D + nn)) * TWOD + h * 128 + kc * 64 + k8 * 8;
                *(uint4*)(sWhi + nn * LDW + k8 * 8) = *(const uint4*)(g_w2t_hi + src);
                *(uint4*)(sWlo + nn * LDW + k8 * 8) = *(const uint4*)(g_w2t_lo + src);
            }
            __syncthreads();
#pragma unroll
            for (int ks = 0; ks < 4; ++ks) {
                wmma::fragment<wmma::matrix_a, 16, 16, 16, __nv_bfloat16, wmma::row_major> ahi[2], alo[2];
                wmma::fragment<wmma::matrix_b, 16, 16, 16, __nv_bfloat16, wmma::col_major> bhi[2], blo[2];
#pragma unroll
                for (int i = 0; i < 2; ++i) {
                    const __nv_bfloat16* pa = sThi + (wr * 32 + i * 16) * LDTH + kc * 64 + ks * 16;
                    wmma::load_matrix_sync(ahi[i], pa, LDTH);
                    wmma::load_matrix_sync(alo[i], pa + (OFF_TLO - OFF_THI) / 2, LDTH);
                }
#pragma unroll
                for (int j = 0; j < 2; ++j) {
                    const __nv_bfloat16* pb = sWhi + (wc * 32 + j * 16) * LDW + ks * 16;
                    wmma::load_matrix_sync(bhi[j], pb, LDW);
                    wmma::load_matrix_sync(blo[j], pb + OFF_WLO_REL / 2, LDW);
                }
#pragma unroll
                for (int i = 0; i < 2; ++i)
#pragma unroll
                    for (int j = 0; j < 2; ++j) {
                        wmma::mma_sync(acc2[i][j], ahi[i], bhi[j], acc2[i][j]);
                        wmma::mma_sync(acc2[i][j], ahi[i], blo[j], acc2[i][j]);
                        wmma::mma_sync(acc2[i][j], alo[i], bhi[j], acc2[i][j]);
                    }
            }
        }
    }

    // stage C2 fp32 into X
    __syncthreads();
#pragma unroll
    for (int i = 0; i < 2; ++i)
#pragma unroll
        for (int j = 0; j < 2; ++j)
            wmma::store_matrix_sync(Xf + (wr * 32 + i * 16) * LDX + wc * 32 + j * 16,
                                    acc2[i][j], LDX, wmma::mem_row_major);
    __syncthreads();

    // ---- epilogue: O = C2 + b2 ----
    for (int i = tid; i < TILE_M * (D / 4); i += NTHR) {
        int r = i >> 5, c4 = i & 31;
        long grow = (long)row0 + r;
        if (grow >= n) continue;
        float4 v = *(float4*)(Xf + r * LDX + c4 * 4);
        float4 o;
        o.x = v.x + sb2[c4 * 4 + 0];
        o.y = v.y + sb2[c4 * 4 + 1];
        o.z = v.z + sb2[c4 * 4 + 2];
        o.w = v.w + sb2[c4 * 4 + 3];
        long off = grow * D + c4 * 4;
        if (last) {
            *(float4*)(out + off) = o;
        } else {
            float4 h;
            h.x = fmaxf(o.x, 0.f); h.y = fmaxf(o.y, 0.f);
            h.z = fmaxf(o.z, 0.f); h.w = fmaxf(o.w, 0.f);
            *(float4*)(g_h + off) = h;
            float4 cv = *(float4*)&sc[c4 * 4];
            *(float4*)(g_agg + off) = f4add(h, cv);
        }
    }
}

// ---------------------------------------------------------------------------
extern "C" void kernel_launch(void* const* d_in, const int* in_sizes, int n_in,
                              void* d_out, int out_size) {
    const int*   x   = (const int*)d_in[0];
    const int*   ei  = (const int*)d_in[1];
    const int*   ea  = (const int*)d_in[2];
    const float* xe1 = (const float*)d_in[3];
    const float* xe2 = (const float*)d_in[4];
    const float* ee1 = (const float*)d_in[5];
    const float* ee2 = (const float*)d_in[6];
    const float* ee3 = (const float*)d_in[7];
    const float* W1  = (const float*)d_in[8];
    const float* b1  = (const float*)d_in[9];
    const float* W2  = (const float*)d_in[10];
    const float* b2  = (const float*)d_in[11];
    float* out = (float*)d_out;
    int n = in_sizes[0] / 2;   // x is [N,2]
    int e = in_sizes[1] / 2;   // edge_index is [2,E]

    cudaFuncSetAttribute(mlp_wmma_kernel,
                         cudaFuncAttributeMaxDynamicSharedMemorySize, SMEM_BYTES);

    prep_w<<<(NLAYER * TWOD * D + 255) / 256, 256>>>(W1, W2);
    embed_kernel<<<(n * (D / 4) + 255) / 256, 256>>>(x, xe1, xe2, ee1, ee2, ee3, n);

    int ntiles = (n + TILE_M - 1) / TILE_M;
    for (int l = 0; l < NLAYER; ++l) {
        scatter_kernel<<<2368, 256>>>(ei, ea,
                                      ee1 + (long)l * 7 * D,
                                      ee2 + (long)l * 3 * D,
                                      ee3 + (long)l * 3 * D, e);
        int last = (l == NLAYER - 1);
        mlp_wmma_kernel<<<ntiles, NTHR, SMEM_BYTES>>>(
            l, last, b1, b2, ee1, ee2, ee3, out, n);
    }
}